// round 11
// baseline (speedup 1.0000x reference)
// R10: (1) qkv GEMM epilogue writes bf16 hi/lo q/k/v directly (no fp32 qkv
// round-trip, no per-tile re-split); (2) attention K/V via cp.async double
// buffer; (3) GEMM 3-stage pipeline. Attention math identical to R9 (679.9us).
#include <cuda_runtime.h>
#include <cuda_bf16.h>
#include <cstdint>

#define SEQ   8192
#define BATCH 2
#define EMB   512
#define NH    16
#define HD    32
#define QKVW  1536
#define MROWS (BATCH * SEQ)
#define KCAT  1536
#define ASTRIDE 40

#define SCALE_L2E (0.17677669529663687f * 1.44269504088896340f)
#define GEMM_SMEM (3 * 2 * 128 * ASTRIDE * 2)   // 3 stages x (A+B) x 128 x 40 bf16

__device__ float g_o[MROWS * EMB];
__device__ int   g_table[SEQ];

__device__ __nv_bfloat16 g_acat[MROWS * KCAT];
__device__ __nv_bfloat16 g_ocat[MROWS * KCAT];
__device__ __nv_bfloat16 g_bq[QKVW * KCAT];
__device__ __nv_bfloat16 g_bo[EMB * KCAT];

// split q/k/v: [row][h*32+d], q pre-scaled by SCALE_L2E
__device__ __nv_bfloat16 g_qh[MROWS * EMB];
__device__ __nv_bfloat16 g_ql[MROWS * EMB];
__device__ __nv_bfloat16 g_kh[MROWS * EMB];
__device__ __nv_bfloat16 g_kl[MROWS * EMB];
__device__ __nv_bfloat16 g_vh[MROWS * EMB];
__device__ __nv_bfloat16 g_vl[MROWS * EMB];

static __device__ __forceinline__ float ex2f(float x) {
    float y; asm("ex2.approx.f32 %0, %1;" : "=f"(y) : "f"(x)); return y;
}
static __device__ __forceinline__ uint32_t smem_u32(const void* p) {
    uint32_t a;
    asm("{ .reg .u64 t; cvta.to.shared.u64 t, %1; cvt.u32.u64 %0, t; }" : "=r"(a) : "l"(p));
    return a;
}
static __device__ __forceinline__ void cp16(uint32_t s, const void* g) {
    asm volatile("cp.async.cg.shared.global [%0], [%1], 16;" :: "r"(s), "l"(g));
}
#define CP_COMMIT() asm volatile("cp.async.commit_group;" ::: "memory")
#define CP_WAIT(n)  asm volatile("cp.async.wait_group %0;" :: "n"(n) : "memory")

static __device__ __forceinline__ void ldmx4(uint32_t* r, uint32_t addr) {
    asm volatile("ldmatrix.sync.aligned.m8n8.x4.shared.b16 {%0,%1,%2,%3}, [%4];"
                 : "=r"(r[0]), "=r"(r[1]), "=r"(r[2]), "=r"(r[3]) : "r"(addr));
}
static __device__ __forceinline__ void ldmx4t(uint32_t* r, uint32_t addr) {
    asm volatile("ldmatrix.sync.aligned.m8n8.x4.trans.shared.b16 {%0,%1,%2,%3}, [%4];"
                 : "=r"(r[0]), "=r"(r[1]), "=r"(r[2]), "=r"(r[3]) : "r"(addr));
}
static __device__ __forceinline__ void mma16816(float* c, const uint32_t* a,
                                                uint32_t b0, uint32_t b1) {
    asm volatile(
        "mma.sync.aligned.m16n8k16.row.col.f32.bf16.bf16.f32 "
        "{%0,%1,%2,%3}, {%4,%5,%6,%7}, {%8,%9}, {%0,%1,%2,%3};"
        : "+f"(c[0]), "+f"(c[1]), "+f"(c[2]), "+f"(c[3])
        : "r"(a[0]), "r"(a[1]), "r"(a[2]), "r"(a[3]), "r"(b0), "r"(b1));
}
static __device__ __forceinline__ uint32_t packbf2(float a, float b) {
    __nv_bfloat162 h = __float22bfloat162_rn(make_float2(a, b));
    return *(uint32_t*)&h;
}

// ---------------------------------------------------------------------------
// Hilbert index-table build (unchanged)
// ---------------------------------------------------------------------------
__device__ __forceinline__ int hilbert_lin(int side, int d) {
    int x = 0, y = 0, t = d;
    for (int s = 1; s < side; s <<= 1) {
        int rx = (t >> 1) & 1;
        int ry = (t ^ rx) & 1;
        if (ry == 0) {
            if (rx == 1) { x = s - 1 - x; y = s - 1 - y; }
            int tmp = x; x = y; y = tmp;
        }
        x += s * rx;
        y += s * ry;
        t >>= 2;
    }
    return y * side + x;
}

__global__ void build_table_kernel() {
    const int posA[4]  = {0, 1024, 3072, 7168};
    const int LA[4]    = {1024, 2048, 4096, 1024};
    const int rA[4]    = {1, 2, 4, 8};
    const int sideA[4] = {32, 64, 64, 32};

    int seg = blockIdx.x;
    int pos = posA[seg], L = LA[seg], r = rA[seg], side = sideA[seg];
    int side2 = side * side;
    int g = L / r;
    int t = threadIdx.x;
    int chunk = side2 >> 10;

    int lin[4];
    int cnt = 0;
    for (int c = 0; c < chunk; c++) {
        lin[c] = hilbert_lin(side, t * chunk + c);
        if (lin[c] < L) cnt++;
    }

    __shared__ int sc[1024];
    sc[t] = cnt;
    __syncthreads();
    for (int off = 1; off < 1024; off <<= 1) {
        int v = (t >= off) ? sc[t - off] : 0;
        __syncthreads();
        sc[t] += v;
        __syncthreads();
    }
    int i = sc[t] - cnt;

    for (int c = 0; c < chunk; c++) {
        if (lin[c] < L) {
            int res = i % r;
            int j   = i / r;
            g_table[pos + res * g + j] = pos + lin[c];
            i++;
        }
    }
}

// ---------------------------------------------------------------------------
// fp32 [M][512] -> concat bf16 [M][1536] = [hi | hi | lo]
// ---------------------------------------------------------------------------
__global__ void split_cat_kernel(const float* __restrict__ in,
                                 __nv_bfloat16* __restrict__ cat) {
    int i4 = (blockIdx.x * 256 + threadIdx.x) * 4;
    int m = i4 >> 9;
    int j = i4 & 511;
    float4 v = *(const float4*)(in + i4);

    __nv_bfloat162 h0, h1, l0, l1;
    h0.x = __float2bfloat16(v.x);  h0.y = __float2bfloat16(v.y);
    h1.x = __float2bfloat16(v.z);  h1.y = __float2bfloat16(v.w);
    l0.x = __float2bfloat16(v.x - __bfloat162float(h0.x));
    l0.y = __float2bfloat16(v.y - __bfloat162float(h0.y));
    l1.x = __float2bfloat16(v.z - __bfloat162float(h1.x));
    l1.y = __float2bfloat16(v.w - __bfloat162float(h1.y));

    __nv_bfloat16* row = cat + (size_t)m * KCAT;
    *(__nv_bfloat162*)(row + j)          = h0;
    *(__nv_bfloat162*)(row + j + 2)      = h1;
    *(__nv_bfloat162*)(row + 512 + j)    = h0;
    *(__nv_bfloat162*)(row + 512 + j + 2)= h1;
    *(__nv_bfloat162*)(row + 1024 + j)   = l0;
    *(__nv_bfloat162*)(row + 1024 + j + 2)= l1;
}

// ---------------------------------------------------------------------------
// fp32 weight [K=512][N] -> transposed concat bf16 [N][1536] = [hi | lo | hi]
// ---------------------------------------------------------------------------
__global__ void transpose_split_cat_kernel(const float* __restrict__ in,
                                           __nv_bfloat16* __restrict__ cat, int N) {
    __shared__ float tile[32][33];
    int n0 = blockIdx.x * 32, k0 = blockIdx.y * 32;
    int tx = threadIdx.x, ty = threadIdx.y;
#pragma unroll
    for (int i = 0; i < 32; i += 8)
        tile[ty + i][tx] = in[(size_t)(k0 + ty + i) * N + n0 + tx];
    __syncthreads();
#pragma unroll
    for (int i = 0; i < 32; i += 8) {
        float v = tile[tx][ty + i];
        __nv_bfloat16 h = __float2bfloat16(v);
        __nv_bfloat16 l = __float2bfloat16(v - __bfloat162float(h));
        size_t o = (size_t)(n0 + ty + i) * KCAT + k0 + tx;
        cat[o]        = h;
        cat[o + 512]  = l;
        cat[o + 1024] = h;
    }
}

__global__ void zero_kernel() {
    int i = (blockIdx.x * 256 + threadIdx.x) * 4;
    *(float4*)(g_o + i) = make_float4(0.f, 0.f, 0.f, 0.f);
}

// ---------------------------------------------------------------------------
// HMMA GEMM, 3-stage cp.async pipeline. MODE 0: C = fp32 + bias (out proj).
// MODE 1: qkv — epilogue splits (acc+bias) [xSCALE_L2E for q] into bf16 hi/lo
// arrays [row][(col%512)]; block's 128-col span lies in one of q/k/v.
// ---------------------------------------------------------------------------
template<int MODE>
__global__ void __launch_bounds__(256) gemm_mma_t(
    const __nv_bfloat16* __restrict__ Acat, const __nv_bfloat16* __restrict__ Bcat,
    const float* __restrict__ bias, float* __restrict__ C, int N,
    __nv_bfloat16* qh, __nv_bfloat16* ql, __nv_bfloat16* kh,
    __nv_bfloat16* kl, __nv_bfloat16* vh, __nv_bfloat16* vl)
{
    extern __shared__ __nv_bfloat16 dsm[];
    uint32_t sA = smem_u32(dsm);                          // 3 x 128 x 40
    uint32_t sB = sA + 3 * 128 * ASTRIDE * 2;

    int t    = threadIdx.x;
    int lane = t & 31;
    int wid  = t >> 5;
    int bm   = blockIdx.y * 128;
    int bn   = blockIdx.x * 128;

    int lr = t >> 2;
    int lc = (t & 3) << 3;

    float acc[4][4][4];
#pragma unroll
    for (int a = 0; a < 4; a++)
#pragma unroll
        for (int b = 0; b < 4; b++)
#pragma unroll
            for (int c = 0; c < 4; c++) acc[a][b][c] = 0.f;

    int wm = wid >> 2, wn = wid & 3;
    int mb = wm * 64, nb = wn * 32;
    int lrow = lane & 15;
    int lcol = (lane >> 4) << 3;

    const int NK = KCAT / 32;   // 48

    // preload stages 0,1
#pragma unroll
    for (int s = 0; s < 2; s++) {
#pragma unroll
        for (int i = 0; i < 2; i++) {
            int r = lr + 64 * i;
            cp16(sA + (uint32_t)((s * 128 + r) * ASTRIDE + lc) * 2,
                 Acat + (size_t)(bm + r) * KCAT + s * 32 + lc);
            cp16(sB + (uint32_t)((s * 128 + r) * ASTRIDE + lc) * 2,
                 Bcat + (size_t)(bn + r) * KCAT + s * 32 + lc);
        }
        CP_COMMIT();
    }

    for (int kc = 0; kc < NK; kc++) {
        int st = kc % 3;
        int pf = kc + 2;
        if (pf < NK) {
            int ps = pf % 3;
#pragma unroll
            for (int i = 0; i < 2; i++) {
                int r = lr + 64 * i;
                cp16(sA + (uint32_t)((ps * 128 + r) * ASTRIDE + lc) * 2,
                     Acat + (size_t)(bm + r) * KCAT + pf * 32 + lc);
                cp16(sB + (uint32_t)((ps * 128 + r) * ASTRIDE + lc) * 2,
                     Bcat + (size_t)(bn + r) * KCAT + pf * 32 + lc);
            }
            CP_COMMIT();
        }
        if (kc < NK - 2)      { CP_WAIT(2); }
        else if (kc == NK - 2){ CP_WAIT(1); }
        else                  { CP_WAIT(0); }
        __syncthreads();

#pragma unroll
        for (int ks = 0; ks < 32; ks += 16) {
            uint32_t av[4][4], bv[2][4];
#pragma unroll
            for (int mt = 0; mt < 4; mt++)
                ldmx4(av[mt], sA + (uint32_t)((st * 128 + mb + mt * 16 + lrow) * ASTRIDE
                                              + ks + lcol) * 2);
#pragma unroll
            for (int pt = 0; pt < 2; pt++)
                ldmx4(bv[pt], sB + (uint32_t)((st * 128 + nb + pt * 16 + lrow) * ASTRIDE
                                              + ks + lcol) * 2);
#pragma unroll
            for (int mt = 0; mt < 4; mt++)
#pragma unroll
                for (int nt = 0; nt < 4; nt++) {
                    uint32_t b0 = bv[nt >> 1][nt & 1];
                    uint32_t b1 = bv[nt >> 1][(nt & 1) + 2];
                    mma16816(acc[mt][nt], av[mt], b0, b1);
                }
        }
        __syncthreads();
    }

    int gr = bm + mb + (lane >> 2);
    int gc = bn + nb + (lane & 3) * 2;

    if (MODE == 0) {
#pragma unroll
        for (int mt = 0; mt < 4; mt++)
#pragma unroll
            for (int nt = 0; nt < 4; nt++) {
                int row = gr + mt * 16;
                int col = gc + nt * 8;
                float b0 = bias[col], b1 = bias[col + 1];
                float2 v0 = make_float2(acc[mt][nt][0] + b0, acc[mt][nt][1] + b1);
                float2 v1 = make_float2(acc[mt][nt][2] + b0, acc[mt][nt][3] + b1);
                *(float2*)(C + (size_t)row * N + col)       = v0;
                *(float2*)(C + (size_t)(row + 8) * N + col) = v1;
            }
    } else {
        int part = bn >> 9;                 // block's 128 cols within one part
        __nv_bfloat16 *ph, *pl;
        if      (part == 0) { ph = qh; pl = ql; }
        else if (part == 1) { ph = kh; pl = kl; }
        else                { ph = vh; pl = vl; }
        float scl = (part == 0) ? SCALE_L2E : 1.0f;
#pragma unroll
        for (int mt = 0; mt < 4; mt++)
#pragma unroll
            for (int nt = 0; nt < 4; nt++) {
                int row  = gr + mt * 16;
                int col  = gc + nt * 8;
                int c512 = col & 511;
                float b0 = bias[col], b1 = bias[col + 1];
                float v00 = (acc[mt][nt][0] + b0) * scl;
                float v01 = (acc[mt][nt][1] + b1) * scl;
                float v10 = (acc[mt][nt][2] + b0) * scl;
                float v11 = (acc[mt][nt][3] + b1) * scl;
                uint32_t h0 = packbf2(v00, v01);
                uint32_t h1 = packbf2(v10, v11);
                __nv_bfloat162 hb0 = *(__nv_bfloat162*)&h0;
                __nv_bfloat162 hb1 = *(__nv_bfloat162*)&h1;
                uint32_t l0 = packbf2(v00 - __bfloat162float(hb0.x),
                                      v01 - __bfloat162float(hb0.y));
                uint32_t l1 = packbf2(v10 - __bfloat162float(hb1.x),
                                      v11 - __bfloat162float(hb1.y));
                *(uint32_t*)(ph + (size_t)row * 512 + c512)       = h0;
                *(uint32_t*)(pl + (size_t)row * 512 + c512)       = l0;
                *(uint32_t*)(ph + (size_t)(row + 8) * 512 + c512) = h1;
                *(uint32_t*)(pl + (size_t)(row + 8) * 512 + c512) = l1;
            }
    }
}

// ---------------------------------------------------------------------------
// HMMA flash attention, 64-key tiles, cp.async fills, double-buffered K/V.
// grid (25,16,2), 256 thr. Q hi/lo staged via cp.async into sm[0] then frags.
// Math identical to R9 (validated 679.9us / 1.04e-5).
// ---------------------------------------------------------------------------
__global__ void __launch_bounds__(256) attn_mma_kernel() {
    __shared__ __nv_bfloat16 sm[2][4][64][ASTRIDE];   // 40960 B

    int x = blockIdx.x, h = blockIdx.y, b = blockIdx.z;
    int seg, tile;
    if      (x < 8)  { seg = 0; tile = x;      }
    else if (x < 16) { seg = 1; tile = x - 8;  }
    else if (x < 24) { seg = 2; tile = x - 16; }
    else             { seg = 3; tile = 0;      }
    int g, base;
    if      (seg == 0) { g = 1024; base = 0; }
    else if (seg == 1) { g = 1024; base = 1024 + (h & 1) * 1024; }
    else if (seg == 2) { g = 1024; base = 3072 + (h & 3) * 1024; }
    else               { g = 128;  base = 7168 + (h & 7) * 128;  }

    int t = threadIdx.x, lane = t & 31, w = t >> 5;
    int qbase = base + tile * 128;
    int hoff  = h * HD;

    // ---- stage Q hi/lo (pre-scaled, pre-split) via cp.async into sm[0] ----
    uint32_t uQhi = smem_u32(sm);                    // rows 0..127
    uint32_t uQlo = uQhi + 128 * ASTRIDE * 2;        // rows 128..255 (still sm[0])
#pragma unroll
    for (int i = 0; i < 2; i++) {
        int task = 2 * t + i;                        // 0..511
        int row = task >> 2, ch = task & 3;
        int gq = g_table[qbase + row];
        size_t off = (size_t)(b * SEQ + gq) * EMB + hoff + ch * 8;
        uint32_t d = (uint32_t)(row * ASTRIDE + ch * 8) * 2;
        cp16(uQhi + d, g_qh + off);
        cp16(uQlo + d, g_ql + off);
    }
    CP_COMMIT();
    CP_WAIT(0);
    __syncthreads();

    uint32_t aqh[2][4], aql[2][4];
    {
        int row = w * 16 + (lane & 15);
        int col = (lane >> 4) << 3;
#pragma unroll
        for (int ks = 0; ks < 2; ks++) {
            ldmx4(aqh[ks], uQhi + (uint32_t)(row * ASTRIDE + ks * 16 + col) * 2);
            ldmx4(aql[ks], uQlo + (uint32_t)(row * ASTRIDE + ks * 16 + col) * 2);
        }
    }
    __syncthreads();

    float m0 = -1e30f, m8 = -1e30f, l0 = 0.f, l8 = 0.f;
    float O[4][4];
#pragma unroll
    for (int i = 0; i < 4; i++)
#pragma unroll
        for (int j = 0; j < 4; j++) O[i][j] = 0.f;

    int nT = g >> 6;
    int frow = t >> 2, farr = t & 3;

    // preload tile 0 into buf 0
    {
        int krow = g_table[base + frow];
        const __nv_bfloat16* src =
            (farr == 0) ? g_kh : (farr == 1) ? g_kl : (farr == 2) ? g_vh : g_vl;
        src += (size_t)(b * SEQ + krow) * EMB + hoff;
        uint32_t dst = smem_u32(&sm[0][farr][frow][0]);
#pragma unroll
        for (int ch = 0; ch < 4; ch++) cp16(dst + ch * 16, src + ch * 8);
        CP_COMMIT();
    }

    for (int it = 0; it < nT; it++) {
        if (it + 1 < nT) {
            int krow = g_table[base + (it + 1) * 64 + frow];
            const __nv_bfloat16* src =
                (farr == 0) ? g_kh : (farr == 1) ? g_kl : (farr == 2) ? g_vh : g_vl;
            src += (size_t)(b * SEQ + krow) * EMB + hoff;
            uint32_t dst = smem_u32(&sm[(it + 1) & 1][farr][frow][0]);
#pragma unroll
            for (int ch = 0; ch < 4; ch++) cp16(dst + ch * 16, src + ch * 8);
            CP_COMMIT();
            CP_WAIT(1);
        } else {
            CP_WAIT(0);
        }
        __syncthreads();

        int bb = it & 1;
        uint32_t uKhi = smem_u32(sm[bb][0]);
        uint32_t uKlo = smem_u32(sm[bb][1]);
        uint32_t uVhi = smem_u32(sm[bb][2]);
        uint32_t uVlo = smem_u32(sm[bb][3]);

        // ---- S = Q·K^T (3 split terms), 8 n-frags ----
        float S[8][4];
#pragma unroll
        for (int i = 0; i < 8; i++)
#pragma unroll
            for (int j = 0; j < 4; j++) S[i][j] = 0.f;

        {
            int krow = lane & 15;
            int kcol = (lane >> 4) << 3;
#pragma unroll
            for (int kg = 0; kg < 4; kg++) {
                uint32_t bkh[2][4], bkl[2][4];
                uint32_t rbase = (uint32_t)((kg * 16 + krow) * ASTRIDE + kcol) * 2;
                ldmx4(bkh[0], uKhi + rbase);
                ldmx4(bkh[1], uKhi + rbase + 32);
                ldmx4(bkl[0], uKlo + rbase);
                ldmx4(bkl[1], uKlo + rbase + 32);
#pragma unroll
                for (int ks = 0; ks < 2; ks++) {
                    mma16816(S[2 * kg],     aqh[ks], bkh[ks][0], bkh[ks][2]);
                    mma16816(S[2 * kg + 1], aqh[ks], bkh[ks][1], bkh[ks][3]);
                    mma16816(S[2 * kg],     aqh[ks], bkl[ks][0], bkl[ks][2]);
                    mma16816(S[2 * kg + 1], aqh[ks], bkl[ks][1], bkl[ks][3]);
                    mma16816(S[2 * kg],     aql[ks], bkh[ks][0], bkh[ks][2]);
                    mma16816(S[2 * kg + 1], aql[ks], bkh[ks][1], bkh[ks][3]);
                }
            }
        }

        // ---- online softmax ----
        float mx0 = -1e30f, mx8 = -1e30f;
#pragma unroll
        for (int nf = 0; nf < 8; nf++) {
            mx0 = fmaxf(mx0, fmaxf(S[nf][0], S[nf][1]));
            mx8 = fmaxf(mx8, fmaxf(S[nf][2], S[nf][3]));
        }
        mx0 = fmaxf(mx0, __shfl_xor_sync(0xffffffffu, mx0, 1));
        mx0 = fmaxf(mx0, __shfl_xor_sync(0xffffffffu, mx0, 2));
        mx8 = fmaxf(mx8, __shfl_xor_sync(0xffffffffu, mx8, 1));
        mx8 = fmaxf(mx8, __shfl_xor_sync(0xffffffffu, mx8, 2));

        float mn0 = fmaxf(m0, mx0), mn8 = fmaxf(m8, mx8);
        float c0 = ex2f(m0 - mn0), c8 = ex2f(m8 - mn8);
        m0 = mn0; m8 = mn8;

        float sum0 = 0.f, sum8 = 0.f;
#pragma unroll
        for (int nf = 0; nf < 8; nf++) {
            S[nf][0] = ex2f(S[nf][0] - mn0);
            S[nf][1] = ex2f(S[nf][1] - mn0);
            S[nf][2] = ex2f(S[nf][2] - mn8);
            S[nf][3] = ex2f(S[nf][3] - mn8);
            sum0 += S[nf][0] + S[nf][1];
            sum8 += S[nf][2] + S[nf][3];
        }
        sum0 += __shfl_xor_sync(0xffffffffu, sum0, 1);
        sum0 += __shfl_xor_sync(0xffffffffu, sum0, 2);
        sum8 += __shfl_xor_sync(0xffffffffu, sum8, 1);
        sum8 += __shfl_xor_sync(0xffffffffu, sum8, 2);
        l0 = l0 * c0 + sum0;
        l8 = l8 * c8 + sum8;
#pragma unroll
        for (int nf = 0; nf < 4; nf++) {
            O[nf][0] *= c0; O[nf][1] *= c0;
            O[nf][2] *= c8; O[nf][3] *= c8;
        }

        // ---- P hi/lo frags from S regs ----
        uint32_t ph01[8], ph23[8], pl01[8], pl23[8];
#pragma unroll
        for (int nf = 0; nf < 8; nf++) {
            uint32_t h01 = packbf2(S[nf][0], S[nf][1]);
            uint32_t h23 = packbf2(S[nf][2], S[nf][3]);
            __nv_bfloat162 hb01 = *(__nv_bfloat162*)&h01;
            __nv_bfloat162 hb23 = *(__nv_bfloat162*)&h23;
            ph01[nf] = h01; ph23[nf] = h23;
            pl01[nf] = packbf2(S[nf][0] - __bfloat162float(hb01.x),
                               S[nf][1] - __bfloat162float(hb01.y));
            pl23[nf] = packbf2(S[nf][2] - __bfloat162float(hb23.x),
                               S[nf][3] - __bfloat162float(hb23.y));
        }

        // ---- O += P·V (3 split terms) ----
        {
            int lr  = lane & 7;
            int sel = lane >> 3;
            int vro = (sel & 1) * 8 + lr;
            int vco = (sel >> 1) * 8;
#pragma unroll
            for (int kk = 0; kk < 4; kk++) {
                uint32_t aphi[4] = {ph01[2 * kk], ph23[2 * kk], ph01[2 * kk + 1], ph23[2 * kk + 1]};
                uint32_t aplo[4] = {pl01[2 * kk], pl23[2 * kk], pl01[2 * kk + 1], pl23[2 * kk + 1]};
                uint32_t bvh[2][4], bvl[2][4];
                uint32_t rb = (uint32_t)((kk * 16 + vro) * ASTRIDE + vco) * 2;
                ldmx4t(bvh[0], uVhi + rb);
                ldmx4t(bvh[1], uVhi + rb + 32);
                ldmx4t(bvl[0], uVlo + rb);
                ldmx4t(bvl[1], uVlo + rb + 32);
#pragma unroll
                for (int dg = 0; dg < 2; dg++) {
                    mma16816(O[2 * dg],     aphi, bvh[dg][0], bvh[dg][1]);
                    mma16816(O[2 * dg + 1], aphi, bvh[dg][2], bvh[dg][3]);
                    mma16816(O[2 * dg],     aplo, bvh[dg][0], bvh[dg][1]);
                    mma16816(O[2 * dg + 1], aplo, bvh[dg][2], bvh[dg][3]);
                    mma16816(O[2 * dg],     aphi, bvl[dg][0], bvl[dg][1]);
                    mma16816(O[2 * dg + 1], aphi, bvl[dg][2], bvl[dg][3]);
                }
            }
        }
        __syncthreads();
    }

    // ---- epilogue: normalize, scatter to g_o ----
    float inv0 = 1.0f / l0, inv8 = 1.0f / l8;
    int r0  = w * 16 + (lane >> 2);
    int gq0 = g_table[qbase + r0];
    int gq8 = g_table[qbase + r0 + 8];
    int c   = (lane & 3) * 2;
    float* o0 = g_o + (size_t)(b * SEQ + gq0) * EMB + hoff + c;
    float* o8 = g_o + (size_t)(b * SEQ + gq8) * EMB + hoff + c;
#pragma unroll
    for (int nf = 0; nf < 4; nf++) {
        *(float2*)(o0 + nf * 8) = make_float2(O[nf][0] * inv0, O[nf][1] * inv0);
        *(float2*)(o8 + nf * 8) = make_float2(O[nf][2] * inv8, O[nf][3] * inv8);
    }
}

// ---------------------------------------------------------------------------
// Launch
// ---------------------------------------------------------------------------
extern "C" void kernel_launch(void* const* d_in, const int* in_sizes, int n_in,
                              void* d_out, int out_size) {
    const float* x     = (const float*)d_in[0];
    const float* w_qkv = (const float*)d_in[1];
    const float* b_qkv = (const float*)d_in[2];
    const float* w_out = (const float*)d_in[3];
    const float* b_out = (const float*)d_in[4];
    float* out = (float*)d_out;

    float* o_ptr = nullptr;
    __nv_bfloat16 *acat, *ocat, *bq, *bo, *qh, *ql, *kh, *kl, *vh, *vl;
    cudaGetSymbolAddress((void**)&o_ptr, g_o);
    cudaGetSymbolAddress((void**)&acat, g_acat);
    cudaGetSymbolAddress((void**)&ocat, g_ocat);
    cudaGetSymbolAddress((void**)&bq,   g_bq);
    cudaGetSymbolAddress((void**)&bo,   g_bo);
    cudaGetSymbolAddress((void**)&qh,   g_qh);
    cudaGetSymbolAddress((void**)&ql,   g_ql);
    cudaGetSymbolAddress((void**)&kh,   g_kh);
    cudaGetSymbolAddress((void**)&kl,   g_kl);
    cudaGetSymbolAddress((void**)&vh,   g_vh);
    cudaGetSymbolAddress((void**)&vl,   g_vl);

    cudaFuncSetAttribute(gemm_mma_t<0>,
                         cudaFuncAttributeMaxDynamicSharedMemorySize, GEMM_SMEM);
    cudaFuncSetAttribute(gemm_mma_t<1>,
                         cudaFuncAttributeMaxDynamicSharedMemorySize, GEMM_SMEM);

    build_table_kernel<<<4, 1024>>>();

    split_cat_kernel<<<(MROWS * EMB) / (4 * 256), 256>>>(x, acat);
    {
        dim3 g1(QKVW / 32, EMB / 32);
        transpose_split_cat_kernel<<<g1, dim3(32, 8)>>>(w_qkv, bq, QKVW);
        dim3 g2(EMB / 32, EMB / 32);
        transpose_split_cat_kernel<<<g2, dim3(32, 8)>>>(w_out, bo, EMB);
    }

    // qkv projection (HMMA, epilogue writes split q/k/v)
    {
        dim3 grid(QKVW / 128, MROWS / 128);
        gemm_mma_t<1><<<grid, 256, GEMM_SMEM>>>(acat, bq, b_qkv, nullptr, QKVW,
                                                qh, ql, kh, kl, vh, vl);
    }

    zero_kernel<<<(MROWS * EMB) / (4 * 256), 256>>>();
    {
        dim3 grid(25, NH, BATCH);
        attn_mma_kernel<<<grid, 256>>>();
    }

    split_cat_kernel<<<(MROWS * EMB) / (4 * 256), 256>>>(o_ptr, ocat);
    {
        dim3 grid(EMB / 128, MROWS / 128);
        gemm_mma_t<0><<<grid, 256, GEMM_SMEM>>>(ocat, bo, b_out, out, EMB,
                                                nullptr, nullptr, nullptr,
                                                nullptr, nullptr, nullptr);
    }
}

// round 14
// speedup vs baseline: 1.0226x; 1.0226x over previous
// R13: R11 with attention fills as plain uint4 LDG+STS (no cp.async in the
// attention kernel — the one structurally novel construct in the twice-failed
// R11/R12 bytes). Keeps the substance: fused MODE-1 GEMM epilogue writes
// pre-split bf16 q/k/v; attention does zero conversion work.
#include <cuda_runtime.h>
#include <cuda_bf16.h>
#include <cstdint>

#define SEQ   8192
#define BATCH 2
#define EMB   512
#define NH    16
#define HD    32
#define QKVW  1536
#define MROWS (BATCH * SEQ)
#define KCAT  1536
#define ASTRIDE 40

#define SCALE_L2E (0.17677669529663687f * 1.44269504088896340f)

__device__ float g_o[MROWS * EMB];
__device__ int   g_table[SEQ];

__device__ __nv_bfloat16 g_acat[MROWS * KCAT];
__device__ __nv_bfloat16 g_ocat[MROWS * KCAT];
__device__ __nv_bfloat16 g_bq[QKVW * KCAT];
__device__ __nv_bfloat16 g_bo[EMB * KCAT];

// split q/k/v: [row][h*32+d], q pre-scaled by SCALE_L2E
__device__ __nv_bfloat16 g_qh[MROWS * EMB];
__device__ __nv_bfloat16 g_ql[MROWS * EMB];
__device__ __nv_bfloat16 g_kh[MROWS * EMB];
__device__ __nv_bfloat16 g_kl[MROWS * EMB];
__device__ __nv_bfloat16 g_vh[MROWS * EMB];
__device__ __nv_bfloat16 g_vl[MROWS * EMB];

static __device__ __forceinline__ float ex2f(float x) {
    float y; asm("ex2.approx.f32 %0, %1;" : "=f"(y) : "f"(x)); return y;
}
static __device__ __forceinline__ uint32_t smem_u32(const void* p) {
    uint32_t a;
    asm("{ .reg .u64 t; cvta.to.shared.u64 t, %1; cvt.u32.u64 %0, t; }" : "=r"(a) : "l"(p));
    return a;
}
static __device__ __forceinline__ void cp16(uint32_t s, const void* g) {
    asm volatile("cp.async.cg.shared.global [%0], [%1], 16;" :: "r"(s), "l"(g));
}
#define CP_COMMIT() asm volatile("cp.async.commit_group;" ::: "memory")
#define CP_WAIT(n)  asm volatile("cp.async.wait_group %0;" :: "n"(n) : "memory")

static __device__ __forceinline__ void ldmx4(uint32_t* r, uint32_t addr) {
    asm volatile("ldmatrix.sync.aligned.m8n8.x4.shared.b16 {%0,%1,%2,%3}, [%4];"
                 : "=r"(r[0]), "=r"(r[1]), "=r"(r[2]), "=r"(r[3]) : "r"(addr));
}
static __device__ __forceinline__ void ldmx4t(uint32_t* r, uint32_t addr) {
    asm volatile("ldmatrix.sync.aligned.m8n8.x4.trans.shared.b16 {%0,%1,%2,%3}, [%4];"
                 : "=r"(r[0]), "=r"(r[1]), "=r"(r[2]), "=r"(r[3]) : "r"(addr));
}
static __device__ __forceinline__ void mma16816(float* c, const uint32_t* a,
                                                uint32_t b0, uint32_t b1) {
    asm volatile(
        "mma.sync.aligned.m16n8k16.row.col.f32.bf16.bf16.f32 "
        "{%0,%1,%2,%3}, {%4,%5,%6,%7}, {%8,%9}, {%0,%1,%2,%3};"
        : "+f"(c[0]), "+f"(c[1]), "+f"(c[2]), "+f"(c[3])
        : "r"(a[0]), "r"(a[1]), "r"(a[2]), "r"(a[3]), "r"(b0), "r"(b1));
}
static __device__ __forceinline__ uint32_t packbf2(float a, float b) {
    __nv_bfloat162 h = __float22bfloat162_rn(make_float2(a, b));
    return *(uint32_t*)&h;
}

// ---------------------------------------------------------------------------
// Hilbert index-table build (unchanged)
// ---------------------------------------------------------------------------
__device__ __forceinline__ int hilbert_lin(int side, int d) {
    int x = 0, y = 0, t = d;
    for (int s = 1; s < side; s <<= 1) {
        int rx = (t >> 1) & 1;
        int ry = (t ^ rx) & 1;
        if (ry == 0) {
            if (rx == 1) { x = s - 1 - x; y = s - 1 - y; }
            int tmp = x; x = y; y = tmp;
        }
        x += s * rx;
        y += s * ry;
        t >>= 2;
    }
    return y * side + x;
}

__global__ void build_table_kernel() {
    const int posA[4]  = {0, 1024, 3072, 7168};
    const int LA[4]    = {1024, 2048, 4096, 1024};
    const int rA[4]    = {1, 2, 4, 8};
    const int sideA[4] = {32, 64, 64, 32};

    int seg = blockIdx.x;
    int pos = posA[seg], L = LA[seg], r = rA[seg], side = sideA[seg];
    int side2 = side * side;
    int g = L / r;
    int t = threadIdx.x;
    int chunk = side2 >> 10;

    int lin[4];
    int cnt = 0;
    for (int c = 0; c < chunk; c++) {
        lin[c] = hilbert_lin(side, t * chunk + c);
        if (lin[c] < L) cnt++;
    }

    __shared__ int sc[1024];
    sc[t] = cnt;
    __syncthreads();
    for (int off = 1; off < 1024; off <<= 1) {
        int v = (t >= off) ? sc[t - off] : 0;
        __syncthreads();
        sc[t] += v;
        __syncthreads();
    }
    int i = sc[t] - cnt;

    for (int c = 0; c < chunk; c++) {
        if (lin[c] < L) {
            int res = i % r;
            int j   = i / r;
            g_table[pos + res * g + j] = pos + lin[c];
            i++;
        }
    }
}

// ---------------------------------------------------------------------------
// fp32 [M][512] -> concat bf16 [M][1536] = [hi | hi | lo]
// ---------------------------------------------------------------------------
__global__ void split_cat_kernel(const float* __restrict__ in,
                                 __nv_bfloat16* __restrict__ cat) {
    int i4 = (blockIdx.x * 256 + threadIdx.x) * 4;
    int m = i4 >> 9;
    int j = i4 & 511;
    float4 v = *(const float4*)(in + i4);

    __nv_bfloat162 h0, h1, l0, l1;
    h0.x = __float2bfloat16(v.x);  h0.y = __float2bfloat16(v.y);
    h1.x = __float2bfloat16(v.z);  h1.y = __float2bfloat16(v.w);
    l0.x = __float2bfloat16(v.x - __bfloat162float(h0.x));
    l0.y = __float2bfloat16(v.y - __bfloat162float(h0.y));
    l1.x = __float2bfloat16(v.z - __bfloat162float(h1.x));
    l1.y = __float2bfloat16(v.w - __bfloat162float(h1.y));

    __nv_bfloat16* row = cat + (size_t)m * KCAT;
    *(__nv_bfloat162*)(row + j)          = h0;
    *(__nv_bfloat162*)(row + j + 2)      = h1;
    *(__nv_bfloat162*)(row + 512 + j)    = h0;
    *(__nv_bfloat162*)(row + 512 + j + 2)= h1;
    *(__nv_bfloat162*)(row + 1024 + j)   = l0;
    *(__nv_bfloat162*)(row + 1024 + j + 2)= l1;
}

// ---------------------------------------------------------------------------
// fp32 weight [K=512][N] -> transposed concat bf16 [N][1536] = [hi | lo | hi]
// ---------------------------------------------------------------------------
__global__ void transpose_split_cat_kernel(const float* __restrict__ in,
                                           __nv_bfloat16* __restrict__ cat, int N) {
    __shared__ float tile[32][33];
    int n0 = blockIdx.x * 32, k0 = blockIdx.y * 32;
    int tx = threadIdx.x, ty = threadIdx.y;
#pragma unroll
    for (int i = 0; i < 32; i += 8)
        tile[ty + i][tx] = in[(size_t)(k0 + ty + i) * N + n0 + tx];
    __syncthreads();
#pragma unroll
    for (int i = 0; i < 32; i += 8) {
        float v = tile[tx][ty + i];
        __nv_bfloat16 h = __float2bfloat16(v);
        __nv_bfloat16 l = __float2bfloat16(v - __bfloat162float(h));
        size_t o = (size_t)(n0 + ty + i) * KCAT + k0 + tx;
        cat[o]        = h;
        cat[o + 512]  = l;
        cat[o + 1024] = h;
    }
}

__global__ void zero_kernel() {
    int i = (blockIdx.x * 256 + threadIdx.x) * 4;
    *(float4*)(g_o + i) = make_float4(0.f, 0.f, 0.f, 0.f);
}

// ---------------------------------------------------------------------------
// HMMA GEMM — R6's validated 2-stage static-smem pipeline, templated epilogue.
// MODE 0: C = fp32 acc + bias (out proj). MODE 1: qkv — epilogue splits
// (acc+bias) [xSCALE_L2E for q] into bf16 hi/lo arrays [row][col%512].
// ---------------------------------------------------------------------------
template<int MODE>
__global__ void __launch_bounds__(256) gemm_mma_t(
    const __nv_bfloat16* __restrict__ Acat, const __nv_bfloat16* __restrict__ Bcat,
    const float* __restrict__ bias, float* __restrict__ C, int N,
    __nv_bfloat16* qh, __nv_bfloat16* ql, __nv_bfloat16* kh,
    __nv_bfloat16* kl, __nv_bfloat16* vh, __nv_bfloat16* vl)
{
    __shared__ __nv_bfloat16 As[2][128][ASTRIDE];
    __shared__ __nv_bfloat16 Bs[2][128][ASTRIDE];

    int t    = threadIdx.x;
    int lane = t & 31;
    int wid  = t >> 5;
    int bm   = blockIdx.y * 128;
    int bn   = blockIdx.x * 128;
    uint32_t sA = smem_u32(As);
    uint32_t sB = smem_u32(Bs);

    int lr = t >> 2;
    int lc = (t & 3) << 3;

    float acc[4][4][4];
#pragma unroll
    for (int a = 0; a < 4; a++)
#pragma unroll
        for (int b = 0; b < 4; b++)
#pragma unroll
            for (int c = 0; c < 4; c++) acc[a][b][c] = 0.f;

    int wm = wid >> 2, wn = wid & 3;
    int mb = wm * 64, nb = wn * 32;
    int lrow = lane & 15;
    int lcol = (lane >> 4) << 3;

    const int NK = KCAT / 32;   // 48

#pragma unroll
    for (int i = 0; i < 2; i++) {
        int r = lr + 64 * i;
        cp16(sA + (uint32_t)((r) * ASTRIDE + lc) * 2,
             Acat + (size_t)(bm + r) * KCAT + lc);
        cp16(sB + (uint32_t)((r) * ASTRIDE + lc) * 2,
             Bcat + (size_t)(bn + r) * KCAT + lc);
    }
    CP_COMMIT();

    for (int kc = 0; kc < NK; kc++) {
        int st = kc & 1;
        if (kc + 1 < NK) {
            int ns = 1 - st;
#pragma unroll
            for (int i = 0; i < 2; i++) {
                int r = lr + 64 * i;
                cp16(sA + (uint32_t)((ns * 128 + r) * ASTRIDE + lc) * 2,
                     Acat + (size_t)(bm + r) * KCAT + (kc + 1) * 32 + lc);
                cp16(sB + (uint32_t)((ns * 128 + r) * ASTRIDE + lc) * 2,
                     Bcat + (size_t)(bn + r) * KCAT + (kc + 1) * 32 + lc);
            }
            CP_COMMIT();
            CP_WAIT(1);
        } else {
            CP_WAIT(0);
        }
        __syncthreads();

#pragma unroll
        for (int ks = 0; ks < 32; ks += 16) {
            uint32_t av[4][4], bv[2][4];
#pragma unroll
            for (int mt = 0; mt < 4; mt++)
                ldmx4(av[mt], sA + (uint32_t)((st * 128 + mb + mt * 16 + lrow) * ASTRIDE
                                              + ks + lcol) * 2);
#pragma unroll
            for (int pt = 0; pt < 2; pt++)
                ldmx4(bv[pt], sB + (uint32_t)((st * 128 + nb + pt * 16 + lrow) * ASTRIDE
                                              + ks + lcol) * 2);
#pragma unroll
            for (int mt = 0; mt < 4; mt++)
#pragma unroll
                for (int nt = 0; nt < 4; nt++) {
                    uint32_t b0 = bv[nt >> 1][nt & 1];
                    uint32_t b1 = bv[nt >> 1][(nt & 1) + 2];
                    mma16816(acc[mt][nt], av[mt], b0, b1);
                }
        }
        __syncthreads();
    }

    int gr = bm + mb + (lane >> 2);
    int gc = bn + nb + (lane & 3) * 2;

    if (MODE == 0) {
#pragma unroll
        for (int mt = 0; mt < 4; mt++)
#pragma unroll
            for (int nt = 0; nt < 4; nt++) {
                int row = gr + mt * 16;
                int col = gc + nt * 8;
                float b0 = bias[col], b1 = bias[col + 1];
                float2 v0 = make_float2(acc[mt][nt][0] + b0, acc[mt][nt][1] + b1);
                float2 v1 = make_float2(acc[mt][nt][2] + b0, acc[mt][nt][3] + b1);
                *(float2*)(C + (size_t)row * N + col)       = v0;
                *(float2*)(C + (size_t)(row + 8) * N + col) = v1;
            }
    } else {
        int part = bn >> 9;
        __nv_bfloat16 *ph, *pl;
        if      (part == 0) { ph = qh; pl = ql; }
        else if (part == 1) { ph = kh; pl = kl; }
        else                { ph = vh; pl = vl; }
        float scl = (part == 0) ? SCALE_L2E : 1.0f;
#pragma unroll
        for (int mt = 0; mt < 4; mt++)
#pragma unroll
            for (int nt = 0; nt < 4; nt++) {
                int row  = gr + mt * 16;
                int col  = gc + nt * 8;
                int c512 = col & 511;
                float b0 = bias[col], b1 = bias[col + 1];
                float v00 = (acc[mt][nt][0] + b0) * scl;
                float v01 = (acc[mt][nt][1] + b1) * scl;
                float v10 = (acc[mt][nt][2] + b0) * scl;
                float v11 = (acc[mt][nt][3] + b1) * scl;
                uint32_t h0 = packbf2(v00, v01);
                uint32_t h1 = packbf2(v10, v11);
                __nv_bfloat162 hb0 = *(__nv_bfloat162*)&h0;
                __nv_bfloat162 hb1 = *(__nv_bfloat162*)&h1;
                uint32_t l0 = packbf2(v00 - __bfloat162float(hb0.x),
                                      v01 - __bfloat162float(hb0.y));
                uint32_t l1 = packbf2(v10 - __bfloat162float(hb1.x),
                                      v11 - __bfloat162float(hb1.y));
                *(uint32_t*)(ph + (size_t)row * 512 + c512)       = h0;
                *(uint32_t*)(pl + (size_t)row * 512 + c512)       = l0;
                *(uint32_t*)(ph + (size_t)(row + 8) * 512 + c512) = h1;
                *(uint32_t*)(pl + (size_t)(row + 8) * 512 + c512) = l1;
            }
    }
}

// ---------------------------------------------------------------------------
// HMMA flash attention — R9 structure (single 20KB buffer, 64-key tiles).
// Fills are plain uint4 LDG + STS from pre-split bf16 q/k/v (no conversion,
// no cp.async in this kernel).
// ---------------------------------------------------------------------------
__global__ void __launch_bounds__(256) attn_mma_kernel() {
    __shared__ __nv_bfloat16 sm[4][64][ASTRIDE];   // 20480 B

    int x = blockIdx.x, h = blockIdx.y, b = blockIdx.z;
    int seg, tile;
    if      (x < 8)  { seg = 0; tile = x;      }
    else if (x < 16) { seg = 1; tile = x - 8;  }
    else if (x < 24) { seg = 2; tile = x - 16; }
    else             { seg = 3; tile = 0;      }
    int g, base;
    if      (seg == 0) { g = 1024; base = 0; }
    else if (seg == 1) { g = 1024; base = 1024 + (h & 1) * 1024; }
    else if (seg == 2) { g = 1024; base = 3072 + (h & 3) * 1024; }
    else               { g = 128;  base = 7168 + (h & 7) * 128;  }

    int t = threadIdx.x, lane = t & 31, w = t >> 5;
    int qbase = base + tile * 128;
    int hoff  = h * HD;

    uint32_t uKhi = smem_u32(sm[0]);
    uint32_t uKlo = smem_u32(sm[1]);
    uint32_t uVhi = smem_u32(sm[2]);
    uint32_t uVlo = smem_u32(sm[3]);

    // ---- stage Q hi/lo (pre-scaled, pre-split): hi rows 0..127 = sm[0..1],
    //      lo rows 0..127 = sm[2..3]. Plain uint4 loads + stores. ----
    {
        char* smc = (char*)sm;
#pragma unroll
        for (int i = 0; i < 2; i++) {
            int task = 2 * t + i;                    // 0..511
            int row = task >> 2, ch = task & 3;
            int gq = g_table[qbase + row];
            size_t off = (size_t)(b * SEQ + gq) * EMB + hoff + ch * 8;
            uint32_t d = (uint32_t)(row * ASTRIDE + ch * 8) * 2;
            uint4 vh = *(const uint4*)(g_qh + off);
            uint4 vl = *(const uint4*)(g_ql + off);
            *(uint4*)(smc + d)                          = vh;   // sm[0..1]
            *(uint4*)(smc + 2 * 64 * ASTRIDE * 2 + d)   = vl;   // sm[2..3]
        }
    }
    __syncthreads();

    uint32_t aqh[2][4], aql[2][4];
    {
        int row = w * 16 + (lane & 15);
        int col = (lane >> 4) << 3;
#pragma unroll
        for (int ks = 0; ks < 2; ks++) {
            ldmx4(aqh[ks], uKhi + (uint32_t)(row * ASTRIDE + ks * 16 + col) * 2);
            ldmx4(aql[ks], uVhi + (uint32_t)(row * ASTRIDE + ks * 16 + col) * 2);
        }
    }
    __syncthreads();

    float m0 = -1e30f, m8 = -1e30f, l0 = 0.f, l8 = 0.f;
    float O[4][4];
#pragma unroll
    for (int i = 0; i < 4; i++)
#pragma unroll
        for (int j = 0; j < 4; j++) O[i][j] = 0.f;

    int frow = t >> 2, farr = t & 3;

    for (int kt = 0; kt < g; kt += 64) {
        // ---- fill 64-row K/V hi/lo tiles: 64B per thread, plain LDG+STS ----
        {
            int krow = g_table[base + kt + frow];
            const __nv_bfloat16* src =
                (farr == 0) ? g_kh : (farr == 1) ? g_kl : (farr == 2) ? g_vh : g_vl;
            src += (size_t)(b * SEQ + krow) * EMB + hoff;
            uint4 v0 = ((const uint4*)src)[0];
            uint4 v1 = ((const uint4*)src)[1];
            uint4 v2 = ((const uint4*)src)[2];
            uint4 v3 = ((const uint4*)src)[3];
            uint4* dst = (uint4*)&sm[farr][frow][0];
            dst[0] = v0; dst[1] = v1; dst[2] = v2; dst[3] = v3;
        }
        __syncthreads();

        // ---- S = Q·K^T (3 split terms), 8 n-frags ----
        float S[8][4];
#pragma unroll
        for (int i = 0; i < 8; i++)
#pragma unroll
            for (int j = 0; j < 4; j++) S[i][j] = 0.f;

        {
            int krow = lane & 15;
            int kcol = (lane >> 4) << 3;
#pragma unroll
            for (int kg = 0; kg < 4; kg++) {
                uint32_t bkh[2][4], bkl[2][4];
                uint32_t rbase = (uint32_t)((kg * 16 + krow) * ASTRIDE + kcol) * 2;
                ldmx4(bkh[0], uKhi + rbase);
                ldmx4(bkh[1], uKhi + rbase + 32);
                ldmx4(bkl[0], uKlo + rbase);
                ldmx4(bkl[1], uKlo + rbase + 32);
#pragma unroll
                for (int ks = 0; ks < 2; ks++) {
                    mma16816(S[2 * kg],     aqh[ks], bkh[ks][0], bkh[ks][2]);
                    mma16816(S[2 * kg + 1], aqh[ks], bkh[ks][1], bkh[ks][3]);
                    mma16816(S[2 * kg],     aqh[ks], bkl[ks][0], bkl[ks][2]);
                    mma16816(S[2 * kg + 1], aqh[ks], bkl[ks][1], bkl[ks][3]);
                    mma16816(S[2 * kg],     aql[ks], bkh[ks][0], bkh[ks][2]);
                    mma16816(S[2 * kg + 1], aql[ks], bkh[ks][1], bkh[ks][3]);
                }
            }
        }

        // ---- online softmax ----
        float mx0 = -1e30f, mx8 = -1e30f;
#pragma unroll
        for (int nf = 0; nf < 8; nf++) {
            mx0 = fmaxf(mx0, fmaxf(S[nf][0], S[nf][1]));
            mx8 = fmaxf(mx8, fmaxf(S[nf][2], S[nf][3]));
        }
        mx0 = fmaxf(mx0, __shfl_xor_sync(0xffffffffu, mx0, 1));
        mx0 = fmaxf(mx0, __shfl_xor_sync(0xffffffffu, mx0, 2));
        mx8 = fmaxf(mx8, __shfl_xor_sync(0xffffffffu, mx8, 1));
        mx8 = fmaxf(mx8, __shfl_xor_sync(0xffffffffu, mx8, 2));

        float mn0 = fmaxf(m0, mx0), mn8 = fmaxf(m8, mx8);
        float c0 = ex2f(m0 - mn0), c8 = ex2f(m8 - mn8);
        m0 = mn0; m8 = mn8;

        float sum0 = 0.f, sum8 = 0.f;
#pragma unroll
        for (int nf = 0; nf < 8; nf++) {
            S[nf][0] = ex2f(S[nf][0] - mn0);
            S[nf][1] = ex2f(S[nf][1] - mn0);
            S[nf][2] = ex2f(S[nf][2] - mn8);
            S[nf][3] = ex2f(S[nf][3] - mn8);
            sum0 += S[nf][0] + S[nf][1];
            sum8 += S[nf][2] + S[nf][3];
        }
        sum0 += __shfl_xor_sync(0xffffffffu, sum0, 1);
        sum0 += __shfl_xor_sync(0xffffffffu, sum0, 2);
        sum8 += __shfl_xor_sync(0xffffffffu, sum8, 1);
        sum8 += __shfl_xor_sync(0xffffffffu, sum8, 2);
        l0 = l0 * c0 + sum0;
        l8 = l8 * c8 + sum8;
#pragma unroll
        for (int nf = 0; nf < 4; nf++) {
            O[nf][0] *= c0; O[nf][1] *= c0;
            O[nf][2] *= c8; O[nf][3] *= c8;
        }

        // ---- P hi/lo frags from S regs ----
        uint32_t ph01[8], ph23[8], pl01[8], pl23[8];
#pragma unroll
        for (int nf = 0; nf < 8; nf++) {
            uint32_t h01 = packbf2(S[nf][0], S[nf][1]);
            uint32_t h23 = packbf2(S[nf][2], S[nf][3]);
            __nv_bfloat162 hb01 = *(__nv_bfloat162*)&h01;
            __nv_bfloat162 hb23 = *(__nv_bfloat162*)&h23;
            ph01[nf] = h01; ph23[nf] = h23;
            pl01[nf] = packbf2(S[nf][0] - __bfloat162float(hb01.x),
                               S[nf][1] - __bfloat162float(hb01.y));
            pl23[nf] = packbf2(S[nf][2] - __bfloat162float(hb23.x),
                               S[nf][3] - __bfloat162float(hb23.y));
        }

        // ---- O += P·V (3 split terms) ----
        {
            int lr  = lane & 7;
            int sel = lane >> 3;
            int vro = (sel & 1) * 8 + lr;
            int vco = (sel >> 1) * 8;
#pragma unroll
            for (int kk = 0; kk < 4; kk++) {
                uint32_t aphi[4] = {ph01[2 * kk], ph23[2 * kk], ph01[2 * kk + 1], ph23[2 * kk + 1]};
                uint32_t aplo[4] = {pl01[2 * kk], pl23[2 * kk], pl01[2 * kk + 1], pl23[2 * kk + 1]};
                uint32_t bvh[2][4], bvl[2][4];
                uint32_t rb = (uint32_t)((kk * 16 + vro) * ASTRIDE + vco) * 2;
                ldmx4t(bvh[0], uVhi + rb);
                ldmx4t(bvh[1], uVhi + rb + 32);
                ldmx4t(bvl[0], uVlo + rb);
                ldmx4t(bvl[1], uVlo + rb + 32);
#pragma unroll
                for (int dg = 0; dg < 2; dg++) {
                    mma16816(O[2 * dg],     aphi, bvh[dg][0], bvh[dg][1]);
                    mma16816(O[2 * dg + 1], aphi, bvh[dg][2], bvh[dg][3]);
                    mma16816(O[2 * dg],     aplo, bvh[dg][0], bvh[dg][1]);
                    mma16816(O[2 * dg + 1], aplo, bvh[dg][2], bvh[dg][3]);
                    mma16816(O[2 * dg],     aphi, bvl[dg][0], bvl[dg][1]);
                    mma16816(O[2 * dg + 1], aphi, bvl[dg][2], bvl[dg][3]);
                }
            }
        }
        __syncthreads();
    }

    // ---- epilogue: normalize, scatter to g_o ----
    float inv0 = 1.0f / l0, inv8 = 1.0f / l8;
    int r0  = w * 16 + (lane >> 2);
    int gq0 = g_table[qbase + r0];
    int gq8 = g_table[qbase + r0 + 8];
    int c   = (lane & 3) * 2;
    float* o0 = g_o + (size_t)(b * SEQ + gq0) * EMB + hoff + c;
    float* o8 = g_o + (size_t)(b * SEQ + gq8) * EMB + hoff + c;
#pragma unroll
    for (int nf = 0; nf < 4; nf++) {
        *(float2*)(o0 + nf * 8) = make_float2(O[nf][0] * inv0, O[nf][1] * inv0);
        *(float2*)(o8 + nf * 8) = make_float2(O[nf][2] * inv8, O[nf][3] * inv8);
    }
}

// ---------------------------------------------------------------------------
// Launch
// ---------------------------------------------------------------------------
extern "C" void kernel_launch(void* const* d_in, const int* in_sizes, int n_in,
                              void* d_out, int out_size) {
    const float* x     = (const float*)d_in[0];
    const float* w_qkv = (const float*)d_in[1];
    const float* b_qkv = (const float*)d_in[2];
    const float* w_out = (const float*)d_in[3];
    const float* b_out = (const float*)d_in[4];
    float* out = (float*)d_out;

    float* o_ptr = nullptr;
    __nv_bfloat16 *acat, *ocat, *bq, *bo, *qh, *ql, *kh, *kl, *vh, *vl;
    cudaGetSymbolAddress((void**)&o_ptr, g_o);
    cudaGetSymbolAddress((void**)&acat, g_acat);
    cudaGetSymbolAddress((void**)&ocat, g_ocat);
    cudaGetSymbolAddress((void**)&bq,   g_bq);
    cudaGetSymbolAddress((void**)&bo,   g_bo);
    cudaGetSymbolAddress((void**)&qh,   g_qh);
    cudaGetSymbolAddress((void**)&ql,   g_ql);
    cudaGetSymbolAddress((void**)&kh,   g_kh);
    cudaGetSymbolAddress((void**)&kl,   g_kl);
    cudaGetSymbolAddress((void**)&vh,   g_vh);
    cudaGetSymbolAddress((void**)&vl,   g_vl);

    build_table_kernel<<<4, 1024>>>();

    split_cat_kernel<<<(MROWS * EMB) / (4 * 256), 256>>>(x, acat);
    {
        dim3 g1(QKVW / 32, EMB / 32);
        transpose_split_cat_kernel<<<g1, dim3(32, 8)>>>(w_qkv, bq, QKVW);
        dim3 g2(EMB / 32, EMB / 32);
        transpose_split_cat_kernel<<<g2, dim3(32, 8)>>>(w_out, bo, EMB);
    }

    // qkv projection (HMMA, fused split epilogue)
    {
        dim3 grid(QKVW / 128, MROWS / 128);
        gemm_mma_t<1><<<grid, 256>>>(acat, bq, b_qkv, nullptr, QKVW,
                                     qh, ql, kh, kl, vh, vl);
    }

    zero_kernel<<<(MROWS * EMB) / (4 * 256), 256>>>();
    {
        dim3 grid(25, NH, BATCH);
        attn_mma_kernel<<<grid, 256>>>();
    }

    split_cat_kernel<<<(MROWS * EMB) / (4 * 256), 256>>>(o_ptr, ocat);
    {
        dim3 grid(EMB / 128, MROWS / 128);
        gemm_mma_t<0><<<grid, 256>>>(ocat, bo, b_out, out, EMB,
                                     nullptr, nullptr, nullptr,
                                     nullptr, nullptr, nullptr);
    }
}

// round 15
// speedup vs baseline: 1.0624x; 1.0389x over previous
// R14: revert to R9 pipeline (680us proven; R13's pre-split was +20us —
// falsified). Attention-only deltas: __launch_bounds__(256,2) to force
// 2 CTAs/SM (R9 needed ~130 regs -> occ was 1), P-frag packing moved inside
// the PV loop to cut ~24 live regs so the 128-reg cap doesn't spill.
#include <cuda_runtime.h>
#include <cuda_bf16.h>
#include <cstdint>

#define SEQ   8192
#define BATCH 2
#define EMB   512
#define NH    16
#define HD    32
#define QKVW  1536
#define MROWS (BATCH * SEQ)
#define KCAT  1536
#define ASTRIDE 40

#define SCALE_L2E (0.17677669529663687f * 1.44269504088896340f)

__device__ float g_qkv[MROWS * QKVW];
__device__ float g_o[MROWS * EMB];
__device__ int   g_table[SEQ];

__device__ __nv_bfloat16 g_acat[MROWS * KCAT];
__device__ __nv_bfloat16 g_ocat[MROWS * KCAT];
__device__ __nv_bfloat16 g_bq[QKVW * KCAT];
__device__ __nv_bfloat16 g_bo[EMB * KCAT];

static __device__ __forceinline__ float ex2f(float x) {
    float y; asm("ex2.approx.f32 %0, %1;" : "=f"(y) : "f"(x)); return y;
}
static __device__ __forceinline__ uint32_t smem_u32(const void* p) {
    uint32_t a;
    asm("{ .reg .u64 t; cvta.to.shared.u64 t, %1; cvt.u32.u64 %0, t; }" : "=r"(a) : "l"(p));
    return a;
}
static __device__ __forceinline__ void cp16(uint32_t s, const void* g) {
    asm volatile("cp.async.cg.shared.global [%0], [%1], 16;" :: "r"(s), "l"(g));
}
#define CP_COMMIT() asm volatile("cp.async.commit_group;" ::: "memory")
#define CP_WAIT(n)  asm volatile("cp.async.wait_group %0;" :: "n"(n) : "memory")

static __device__ __forceinline__ void ldmx4(uint32_t* r, uint32_t addr) {
    asm volatile("ldmatrix.sync.aligned.m8n8.x4.shared.b16 {%0,%1,%2,%3}, [%4];"
                 : "=r"(r[0]), "=r"(r[1]), "=r"(r[2]), "=r"(r[3]) : "r"(addr));
}
static __device__ __forceinline__ void ldmx4t(uint32_t* r, uint32_t addr) {
    asm volatile("ldmatrix.sync.aligned.m8n8.x4.trans.shared.b16 {%0,%1,%2,%3}, [%4];"
                 : "=r"(r[0]), "=r"(r[1]), "=r"(r[2]), "=r"(r[3]) : "r"(addr));
}
static __device__ __forceinline__ void mma16816(float* c, const uint32_t* a,
                                                uint32_t b0, uint32_t b1) {
    asm volatile(
        "mma.sync.aligned.m16n8k16.row.col.f32.bf16.bf16.f32 "
        "{%0,%1,%2,%3}, {%4,%5,%6,%7}, {%8,%9}, {%0,%1,%2,%3};"
        : "+f"(c[0]), "+f"(c[1]), "+f"(c[2]), "+f"(c[3])
        : "r"(a[0]), "r"(a[1]), "r"(a[2]), "r"(a[3]), "r"(b0), "r"(b1));
}
static __device__ __forceinline__ uint32_t packbf2(float a, float b) {
    __nv_bfloat162 h = __float22bfloat162_rn(make_float2(a, b));
    return *(uint32_t*)&h;
}

// ---------------------------------------------------------------------------
// Hilbert index-table build (unchanged)
// ---------------------------------------------------------------------------
__device__ __forceinline__ int hilbert_lin(int side, int d) {
    int x = 0, y = 0, t = d;
    for (int s = 1; s < side; s <<= 1) {
        int rx = (t >> 1) & 1;
        int ry = (t ^ rx) & 1;
        if (ry == 0) {
            if (rx == 1) { x = s - 1 - x; y = s - 1 - y; }
            int tmp = x; x = y; y = tmp;
        }
        x += s * rx;
        y += s * ry;
        t >>= 2;
    }
    return y * side + x;
}

__global__ void build_table_kernel() {
    const int posA[4]  = {0, 1024, 3072, 7168};
    const int LA[4]    = {1024, 2048, 4096, 1024};
    const int rA[4]    = {1, 2, 4, 8};
    const int sideA[4] = {32, 64, 64, 32};

    int seg = blockIdx.x;
    int pos = posA[seg], L = LA[seg], r = rA[seg], side = sideA[seg];
    int side2 = side * side;
    int g = L / r;
    int t = threadIdx.x;
    int chunk = side2 >> 10;

    int lin[4];
    int cnt = 0;
    for (int c = 0; c < chunk; c++) {
        lin[c] = hilbert_lin(side, t * chunk + c);
        if (lin[c] < L) cnt++;
    }

    __shared__ int sc[1024];
    sc[t] = cnt;
    __syncthreads();
    for (int off = 1; off < 1024; off <<= 1) {
        int v = (t >= off) ? sc[t - off] : 0;
        __syncthreads();
        sc[t] += v;
        __syncthreads();
    }
    int i = sc[t] - cnt;

    for (int c = 0; c < chunk; c++) {
        if (lin[c] < L) {
            int res = i % r;
            int j   = i / r;
            g_table[pos + res * g + j] = pos + lin[c];
            i++;
        }
    }
}

// ---------------------------------------------------------------------------
// fp32 [M][512] -> concat bf16 [M][1536] = [hi | hi | lo]
// ---------------------------------------------------------------------------
__global__ void split_cat_kernel(const float* __restrict__ in,
                                 __nv_bfloat16* __restrict__ cat) {
    int i4 = (blockIdx.x * 256 + threadIdx.x) * 4;
    int m = i4 >> 9;
    int j = i4 & 511;
    float4 v = *(const float4*)(in + i4);

    __nv_bfloat162 h0, h1, l0, l1;
    h0.x = __float2bfloat16(v.x);  h0.y = __float2bfloat16(v.y);
    h1.x = __float2bfloat16(v.z);  h1.y = __float2bfloat16(v.w);
    l0.x = __float2bfloat16(v.x - __bfloat162float(h0.x));
    l0.y = __float2bfloat16(v.y - __bfloat162float(h0.y));
    l1.x = __float2bfloat16(v.z - __bfloat162float(h1.x));
    l1.y = __float2bfloat16(v.w - __bfloat162float(h1.y));

    __nv_bfloat16* row = cat + (size_t)m * KCAT;
    *(__nv_bfloat162*)(row + j)          = h0;
    *(__nv_bfloat162*)(row + j + 2)      = h1;
    *(__nv_bfloat162*)(row + 512 + j)    = h0;
    *(__nv_bfloat162*)(row + 512 + j + 2)= h1;
    *(__nv_bfloat162*)(row + 1024 + j)   = l0;
    *(__nv_bfloat162*)(row + 1024 + j + 2)= l1;
}

// ---------------------------------------------------------------------------
// fp32 weight [K=512][N] -> transposed concat bf16 [N][1536] = [hi | lo | hi]
// ---------------------------------------------------------------------------
__global__ void transpose_split_cat_kernel(const float* __restrict__ in,
                                           __nv_bfloat16* __restrict__ cat, int N) {
    __shared__ float tile[32][33];
    int n0 = blockIdx.x * 32, k0 = blockIdx.y * 32;
    int tx = threadIdx.x, ty = threadIdx.y;
#pragma unroll
    for (int i = 0; i < 32; i += 8)
        tile[ty + i][tx] = in[(size_t)(k0 + ty + i) * N + n0 + tx];
    __syncthreads();
#pragma unroll
    for (int i = 0; i < 32; i += 8) {
        float v = tile[tx][ty + i];
        __nv_bfloat16 h = __float2bfloat16(v);
        __nv_bfloat16 l = __float2bfloat16(v - __bfloat162float(h));
        size_t o = (size_t)(n0 + ty + i) * KCAT + k0 + tx;
        cat[o]        = h;
        cat[o + 512]  = l;
        cat[o + 1024] = h;
    }
}

__global__ void zero_kernel() {
    int i = (blockIdx.x * 256 + threadIdx.x) * 4;
    *(float4*)(g_o + i) = make_float4(0.f, 0.f, 0.f, 0.f);
}

// ---------------------------------------------------------------------------
// HMMA GEMM (R6-validated, fp32+bias output)
// ---------------------------------------------------------------------------
__global__ void __launch_bounds__(256) gemm_mma_kernel(
    const __nv_bfloat16* __restrict__ Acat, const __nv_bfloat16* __restrict__ Bcat,
    const float* __restrict__ bias, float* __restrict__ C, int N)
{
    __shared__ __nv_bfloat16 As[2][128][ASTRIDE];
    __shared__ __nv_bfloat16 Bs[2][128][ASTRIDE];

    int t    = threadIdx.x;
    int lane = t & 31;
    int wid  = t >> 5;
    int bm   = blockIdx.y * 128;
    int bn   = blockIdx.x * 128;
    uint32_t sA = smem_u32(As);
    uint32_t sB = smem_u32(Bs);

    int lr = t >> 2;
    int lc = (t & 3) << 3;

    float acc[4][4][4];
#pragma unroll
    for (int a = 0; a < 4; a++)
#pragma unroll
        for (int b = 0; b < 4; b++)
#pragma unroll
            for (int c = 0; c < 4; c++) acc[a][b][c] = 0.f;

    int wm = wid >> 2, wn = wid & 3;
    int mb = wm * 64, nb = wn * 32;
    int lrow = lane & 15;
    int lcol = (lane >> 4) << 3;

    const int NK = KCAT / 32;

#pragma unroll
    for (int i = 0; i < 2; i++) {
        int r = lr + 64 * i;
        cp16(sA + (uint32_t)((r) * ASTRIDE + lc) * 2,
             Acat + (size_t)(bm + r) * KCAT + lc);
        cp16(sB + (uint32_t)((r) * ASTRIDE + lc) * 2,
             Bcat + (size_t)(bn + r) * KCAT + lc);
    }
    CP_COMMIT();

    for (int kc = 0; kc < NK; kc++) {
        int st = kc & 1;
        if (kc + 1 < NK) {
            int ns = 1 - st;
#pragma unroll
            for (int i = 0; i < 2; i++) {
                int r = lr + 64 * i;
                cp16(sA + (uint32_t)((ns * 128 + r) * ASTRIDE + lc) * 2,
                     Acat + (size_t)(bm + r) * KCAT + (kc + 1) * 32 + lc);
                cp16(sB + (uint32_t)((ns * 128 + r) * ASTRIDE + lc) * 2,
                     Bcat + (size_t)(bn + r) * KCAT + (kc + 1) * 32 + lc);
            }
            CP_COMMIT();
            CP_WAIT(1);
        } else {
            CP_WAIT(0);
        }
        __syncthreads();

#pragma unroll
        for (int ks = 0; ks < 32; ks += 16) {
            uint32_t av[4][4], bv[2][4];
#pragma unroll
            for (int mt = 0; mt < 4; mt++)
                ldmx4(av[mt], sA + (uint32_t)((st * 128 + mb + mt * 16 + lrow) * ASTRIDE
                                              + ks + lcol) * 2);
#pragma unroll
            for (int pt = 0; pt < 2; pt++)
                ldmx4(bv[pt], sB + (uint32_t)((st * 128 + nb + pt * 16 + lrow) * ASTRIDE
                                              + ks + lcol) * 2);
#pragma unroll
            for (int mt = 0; mt < 4; mt++)
#pragma unroll
                for (int nt = 0; nt < 4; nt++) {
                    uint32_t b0 = bv[nt >> 1][nt & 1];
                    uint32_t b1 = bv[nt >> 1][(nt & 1) + 2];
                    mma16816(acc[mt][nt], av[mt], b0, b1);
                }
        }
        __syncthreads();
    }

    int gr = bm + mb + (lane >> 2);
    int gc = bn + nb + (lane & 3) * 2;
#pragma unroll
    for (int mt = 0; mt < 4; mt++)
#pragma unroll
        for (int nt = 0; nt < 4; nt++) {
            int row = gr + mt * 16;
            int col = gc + nt * 8;
            float b0 = bias[col], b1 = bias[col + 1];
            float2 v0 = make_float2(acc[mt][nt][0] + b0, acc[mt][nt][1] + b1);
            float2 v1 = make_float2(acc[mt][nt][2] + b0, acc[mt][nt][3] + b1);
            *(float2*)(C + (size_t)row * N + col)       = v0;
            *(float2*)(C + (size_t)(row + 8) * N + col) = v1;
        }
}

// ---------------------------------------------------------------------------
// HMMA flash attention — R9 structure (64-key tiles, 20KB smem, conversion
// fills from fp32 g_qkv). Deltas: launch_bounds(256,2) for 2 CTAs/SM;
// P-frag packing inlined in the PV loop (same math, smaller live range).
// ---------------------------------------------------------------------------
__device__ __forceinline__ void load_split16(const float* src, float scale,
                                             __nv_bfloat16* dhi, __nv_bfloat16* dlo) {
#pragma unroll
    for (int i = 0; i < 4; i++) {
        float4 v = ((const float4*)src)[i];
        v.x *= scale; v.y *= scale; v.z *= scale; v.w *= scale;
        __nv_bfloat162 h0, h1, l0, l1;
        h0.x = __float2bfloat16(v.x);  h0.y = __float2bfloat16(v.y);
        h1.x = __float2bfloat16(v.z);  h1.y = __float2bfloat16(v.w);
        l0.x = __float2bfloat16(v.x - __bfloat162float(h0.x));
        l0.y = __float2bfloat16(v.y - __bfloat162float(h0.y));
        l1.x = __float2bfloat16(v.z - __bfloat162float(h1.x));
        l1.y = __float2bfloat16(v.w - __bfloat162float(h1.y));
        ((__nv_bfloat162*)dhi)[i * 2]     = h0;
        ((__nv_bfloat162*)dhi)[i * 2 + 1] = h1;
        ((__nv_bfloat162*)dlo)[i * 2]     = l0;
        ((__nv_bfloat162*)dlo)[i * 2 + 1] = l1;
    }
}

__global__ void __launch_bounds__(256, 2) attn_mma_kernel() {
    __shared__ __nv_bfloat16 sm[4][64][ASTRIDE];   // 20480 B

    int x = blockIdx.x, h = blockIdx.y, b = blockIdx.z;
    int seg, tile;
    if      (x < 8)  { seg = 0; tile = x;      }
    else if (x < 16) { seg = 1; tile = x - 8;  }
    else if (x < 24) { seg = 2; tile = x - 16; }
    else             { seg = 3; tile = 0;      }
    int g, base;
    if      (seg == 0) { g = 1024; base = 0; }
    else if (seg == 1) { g = 1024; base = 1024 + (h & 1) * 1024; }
    else if (seg == 2) { g = 1024; base = 3072 + (h & 3) * 1024; }
    else               { g = 128;  base = 7168 + (h & 7) * 128;  }

    int t = threadIdx.x, lane = t & 31, w = t >> 5;
    uint32_t uKhi = smem_u32(sm[0]);
    uint32_t uKlo = smem_u32(sm[1]);
    uint32_t uVhi = smem_u32(sm[2]);
    uint32_t uVlo = smem_u32(sm[3]);
    int qbase = base + tile * 128;

    // ---- stage all 128 Q rows: hi in sm[0..1], lo in sm[2..3] ----
    {
        int fr = t >> 1, fh = t & 1;
        int gq = g_table[qbase + fr];
        const float* qp = g_qkv + (size_t)(b * SEQ + gq) * QKVW + h * HD + fh * 16;
        __nv_bfloat16* qhi = &((__nv_bfloat16(*)[ASTRIDE])sm[0])[fr][fh * 16];
        __nv_bfloat16* qlo = &((__nv_bfloat16(*)[ASTRIDE])sm[2])[fr][fh * 16];
        load_split16(qp, SCALE_L2E, qhi, qlo);
    }
    __syncthreads();
    uint32_t aqh[2][4], aql[2][4];
    {
        int row = w * 16 + (lane & 15);
        int col = (lane >> 4) << 3;
#pragma unroll
        for (int ks = 0; ks < 2; ks++) {
            ldmx4(aqh[ks], uKhi + (uint32_t)(row * ASTRIDE + ks * 16 + col) * 2);
            ldmx4(aql[ks], uVhi + (uint32_t)(row * ASTRIDE + ks * 16 + col) * 2);
        }
    }
    __syncthreads();

    float m0 = -1e30f, m8 = -1e30f, l0 = 0.f, l8 = 0.f;
    float O[4][4];
#pragma unroll
    for (int i = 0; i < 4; i++)
#pragma unroll
        for (int j = 0; j < 4; j++) O[i][j] = 0.f;

    for (int kt = 0; kt < g; kt += 64) {
        // ---- fill 64-row K/V hi/lo tiles: one load_split16 per thread ----
        {
            int fr2 = t >> 2, fq = t & 3;
            int kidx = g_table[base + kt + fr2];
            const float* kp = g_qkv + (size_t)(b * SEQ + kidx) * QKVW + EMB
                            + h * HD + (fq & 1) * 16;
            if (fq < 2)
                load_split16(kp, 1.0f, &sm[0][fr2][(fq & 1) * 16], &sm[1][fr2][(fq & 1) * 16]);
            else
                load_split16(kp + EMB, 1.0f, &sm[2][fr2][(fq & 1) * 16], &sm[3][fr2][(fq & 1) * 16]);
        }
        __syncthreads();

        // ---- S = Q·K^T (3 split terms), 8 n-frags ----
        float S[8][4];
#pragma unroll
        for (int i = 0; i < 8; i++)
#pragma unroll
            for (int j = 0; j < 4; j++) S[i][j] = 0.f;

        {
            int krow = lane & 15;
            int kcol = (lane >> 4) << 3;
#pragma unroll
            for (int kg = 0; kg < 4; kg++) {
                uint32_t bkh[2][4], bkl[2][4];
                uint32_t rbase = (uint32_t)((kg * 16 + krow) * ASTRIDE + kcol) * 2;
                ldmx4(bkh[0], uKhi + rbase);
                ldmx4(bkh[1], uKhi + rbase + 32);
                ldmx4(bkl[0], uKlo + rbase);
                ldmx4(bkl[1], uKlo + rbase + 32);
#pragma unroll
                for (int ks = 0; ks < 2; ks++) {
                    mma16816(S[2 * kg],     aqh[ks], bkh[ks][0], bkh[ks][2]);
                    mma16816(S[2 * kg + 1], aqh[ks], bkh[ks][1], bkh[ks][3]);
                    mma16816(S[2 * kg],     aqh[ks], bkl[ks][0], bkl[ks][2]);
                    mma16816(S[2 * kg + 1], aqh[ks], bkl[ks][1], bkl[ks][3]);
                    mma16816(S[2 * kg],     aql[ks], bkh[ks][0], bkh[ks][2]);
                    mma16816(S[2 * kg + 1], aql[ks], bkh[ks][1], bkh[ks][3]);
                }
            }
        }

        // ---- online softmax ----
        float mx0 = -1e30f, mx8 = -1e30f;
#pragma unroll
        for (int nf = 0; nf < 8; nf++) {
            mx0 = fmaxf(mx0, fmaxf(S[nf][0], S[nf][1]));
            mx8 = fmaxf(mx8, fmaxf(S[nf][2], S[nf][3]));
        }
        mx0 = fmaxf(mx0, __shfl_xor_sync(0xffffffffu, mx0, 1));
        mx0 = fmaxf(mx0, __shfl_xor_sync(0xffffffffu, mx0, 2));
        mx8 = fmaxf(mx8, __shfl_xor_sync(0xffffffffu, mx8, 1));
        mx8 = fmaxf(mx8, __shfl_xor_sync(0xffffffffu, mx8, 2));

        float mn0 = fmaxf(m0, mx0), mn8 = fmaxf(m8, mx8);
        float c0 = ex2f(m0 - mn0), c8 = ex2f(m8 - mn8);
        m0 = mn0; m8 = mn8;

        float sum0 = 0.f, sum8 = 0.f;
#pragma unroll
        for (int nf = 0; nf < 8; nf++) {
            S[nf][0] = ex2f(S[nf][0] - mn0);
            S[nf][1] = ex2f(S[nf][1] - mn0);
            S[nf][2] = ex2f(S[nf][2] - mn8);
            S[nf][3] = ex2f(S[nf][3] - mn8);
            sum0 += S[nf][0] + S[nf][1];
            sum8 += S[nf][2] + S[nf][3];
        }
        sum0 += __shfl_xor_sync(0xffffffffu, sum0, 1);
        sum0 += __shfl_xor_sync(0xffffffffu, sum0, 2);
        sum8 += __shfl_xor_sync(0xffffffffu, sum8, 1);
        sum8 += __shfl_xor_sync(0xffffffffu, sum8, 2);
        l0 = l0 * c0 + sum0;
        l8 = l8 * c8 + sum8;
#pragma unroll
        for (int nf = 0; nf < 4; nf++) {
            O[nf][0] *= c0; O[nf][1] *= c0;
            O[nf][2] *= c8; O[nf][3] *= c8;
        }

        // ---- O += P·V (3 split terms), P frags packed per-iteration ----
        {
            int lr  = lane & 7;
            int sel = lane >> 3;
            int vro = (sel & 1) * 8 + lr;
            int vco = (sel >> 1) * 8;
#pragma unroll
            for (int kk = 0; kk < 4; kk++) {
                int nf0 = 2 * kk, nf1 = 2 * kk + 1;
                uint32_t aphi[4], aplo[4];
                uint32_t h0 = packbf2(S[nf0][0], S[nf0][1]);
                uint32_t h1 = packbf2(S[nf0][2], S[nf0][3]);
                uint32_t h2 = packbf2(S[nf1][0], S[nf1][1]);
                uint32_t h3 = packbf2(S[nf1][2], S[nf1][3]);
                aphi[0] = h0; aphi[1] = h1; aphi[2] = h2; aphi[3] = h3;
                __nv_bfloat162 b0 = *(__nv_bfloat162*)&h0;
                __nv_bfloat162 b1 = *(__nv_bfloat162*)&h1;
                __nv_bfloat162 b2 = *(__nv_bfloat162*)&h2;
                __nv_bfloat162 b3 = *(__nv_bfloat162*)&h3;
                aplo[0] = packbf2(S[nf0][0] - __bfloat162float(b0.x),
                                  S[nf0][1] - __bfloat162float(b0.y));
                aplo[1] = packbf2(S[nf0][2] - __bfloat162float(b1.x),
                                  S[nf0][3] - __bfloat162float(b1.y));
                aplo[2] = packbf2(S[nf1][0] - __bfloat162float(b2.x),
                                  S[nf1][1] - __bfloat162float(b2.y));
                aplo[3] = packbf2(S[nf1][2] - __bfloat162float(b3.x),
                                  S[nf1][3] - __bfloat162float(b3.y));

                uint32_t bvh[2][4], bvl[2][4];
                uint32_t rb = (uint32_t)((kk * 16 + vro) * ASTRIDE + vco) * 2;
                ldmx4t(bvh[0], uVhi + rb);
                ldmx4t(bvh[1], uVhi + rb + 32);
                ldmx4t(bvl[0], uVlo + rb);
                ldmx4t(bvl[1], uVlo + rb + 32);
#pragma unroll
                for (int dg = 0; dg < 2; dg++) {
                    mma16816(O[2 * dg],     aphi, bvh[dg][0], bvh[dg][1]);
                    mma16816(O[2 * dg + 1], aphi, bvh[dg][2], bvh[dg][3]);
                    mma16816(O[2 * dg],     aplo, bvh[dg][0], bvh[dg][1]);
                    mma16816(O[2 * dg + 1], aplo, bvh[dg][2], bvh[dg][3]);
                    mma16816(O[2 * dg],     aphi, bvl[dg][0], bvl[dg][1]);
                    mma16816(O[2 * dg + 1], aphi, bvl[dg][2], bvl[dg][3]);
                }
            }
        }
        __syncthreads();
    }

    // ---- epilogue: normalize, scatter to g_o ----
    float inv0 = 1.0f / l0, inv8 = 1.0f / l8;
    int r0  = w * 16 + (lane >> 2);
    int gq0 = g_table[qbase + r0];
    int gq8 = g_table[qbase + r0 + 8];
    int c   = (lane & 3) * 2;
    float* o0 = g_o + (size_t)(b * SEQ + gq0) * EMB + h * HD + c;
    float* o8 = g_o + (size_t)(b * SEQ + gq8) * EMB + h * HD + c;
#pragma unroll
    for (int nf = 0; nf < 4; nf++) {
        *(float2*)(o0 + nf * 8) = make_float2(O[nf][0] * inv0, O[nf][1] * inv0);
        *(float2*)(o8 + nf * 8) = make_float2(O[nf][2] * inv8, O[nf][3] * inv8);
    }
}

// ---------------------------------------------------------------------------
// Launch
// ---------------------------------------------------------------------------
extern "C" void kernel_launch(void* const* d_in, const int* in_sizes, int n_in,
                              void* d_out, int out_size) {
    const float* x     = (const float*)d_in[0];
    const float* w_qkv = (const float*)d_in[1];
    const float* b_qkv = (const float*)d_in[2];
    const float* w_out = (const float*)d_in[3];
    const float* b_out = (const float*)d_in[4];
    float* out = (float*)d_out;

    float *qkv_ptr = nullptr, *o_ptr = nullptr;
    __nv_bfloat16 *acat, *ocat, *bq, *bo;
    cudaGetSymbolAddress((void**)&qkv_ptr, g_qkv);
    cudaGetSymbolAddress((void**)&o_ptr,   g_o);
    cudaGetSymbolAddress((void**)&acat, g_acat);
    cudaGetSymbolAddress((void**)&ocat, g_ocat);
    cudaGetSymbolAddress((void**)&bq,   g_bq);
    cudaGetSymbolAddress((void**)&bo,   g_bo);

    build_table_kernel<<<4, 1024>>>();

    split_cat_kernel<<<(MROWS * EMB) / (4 * 256), 256>>>(x, acat);
    {
        dim3 g1(QKVW / 32, EMB / 32);
        transpose_split_cat_kernel<<<g1, dim3(32, 8)>>>(w_qkv, bq, QKVW);
        dim3 g2(EMB / 32, EMB / 32);
        transpose_split_cat_kernel<<<g2, dim3(32, 8)>>>(w_out, bo, EMB);
    }

    {
        dim3 grid(QKVW / 128, MROWS / 128);
        gemm_mma_kernel<<<grid, 256>>>(acat, bq, b_qkv, qkv_ptr, QKVW);
    }

    zero_kernel<<<(MROWS * EMB) / (4 * 256), 256>>>();
    {
        dim3 grid(25, NH, BATCH);
        attn_mma_kernel<<<grid, 256>>>();
    }

    split_cat_kernel<<<(MROWS * EMB) / (4 * 256), 256>>>(o_ptr, ocat);
    {
        dim3 grid(EMB / 128, MROWS / 128);
        gemm_mma_kernel<<<grid, 256>>>(ocat, bo, b_out, out, EMB);
    }
}